// round 14
// baseline (speedup 1.0000x reference)
#include <cuda_runtime.h>
#include <math.h>

#define VOCAB   32000
#define V4      8000                 // float4 per row
#define NROWS   4092                 // 4 * 1023
#define SEQ     1024
#define TPB     1024
#define TAILQ   (V4 - 7 * TPB)       // 832 tail quads (= 26 full warps)
#define MAXCTA  256

__device__ double   g_part[MAXCTA];
__device__ unsigned g_cnt = 0;

typedef unsigned long long u64;

// raw MUFU.LG2 (full-range log2 approx, single instruction)
__device__ __forceinline__ float lg2(float x) {
    float r; asm("lg2.approx.f32 %0, %1;" : "=f"(r) : "f"(x)); return r;
}

// L2 evict-first access policy (created once per thread; uniform)
__device__ __forceinline__ u64 mk_policy() {
    u64 pol;
    asm volatile("createpolicy.fractional.L2::evict_first.b64 %0, 1.0;" : "=l"(pol));
    return pol;
}

// streaming 128-bit load: non-coherent path, L2 evict-first, 256B L2 prefetch
__device__ __forceinline__ float4 ldstream(const float4* a, u64 pol) {
    float4 v;
    asm volatile("ld.global.nc.L2::cache_hint.L2::256B.v4.f32 {%0,%1,%2,%3}, [%4], %5;"
                 : "=f"(v.x), "=f"(v.y), "=f"(v.z), "=f"(v.w)
                 : "l"(a), "l"(pol));
    return v;
}

__device__ __forceinline__ void pf_l2(const void* ptr) {
    asm volatile("prefetch.global.L2 [%0];" :: "l"(ptr));
}

// scalar fast log (prologue only): degree-5, |abs err| <= 2e-4
__device__ __forceinline__ float lnfast(float x) {
    int i = __float_as_int(x);
    int k = (i - 0x3F2AAAAB) & 0xFF800000;
    float f = __int_as_float(i - k) - 1.0f;
    float P = 0.2f;
    P = fmaf(P, f, -0.25f);
    P = fmaf(P, f,  0.33333334f);
    P = fmaf(P, f, -0.5f);
    P = fmaf(P, f,  1.0f);
    return fmaf(f, P, (float)k * 8.2629582e-8f);
}

__device__ __forceinline__ float warp_sum(float v) {
    #pragma unroll
    for (int o = 16; o; o >>= 1) v += __shfl_xor_sync(0xFFFFFFFFu, v, o);
    return v;
}
__device__ __forceinline__ double warp_sum_d(double v) {
    #pragma unroll
    for (int o = 16; o; o >>= 1) v += __shfl_xor_sync(0xFFFFFFFFu, v, o);
    return v;
}

// one quad: 2-accumulator form
__device__ __forceinline__ void proc_quad(float4 v, float4 w, float& a0, float& a1) {
    a0 = fmaf(w.x, lg2(v.x), a0);
    a1 = fmaf(w.y, lg2(v.y), a1);
    a0 = fmaf(w.z, lg2(v.z), a0);
    a1 = fmaf(w.w, lg2(v.w), a1);
}

// row -> base quad pointer ( b*1024 + t = row + row/1023 )
__device__ __forceinline__ const float4* row_ptr(const float* p, int row) {
    int off = row + row / 1023;
    return reinterpret_cast<const float4*>(p + (size_t)off * VOCAB);
}

__global__ void __launch_bounds__(TPB, 1)
main_kernel(const float* __restrict__ p,
            const int*   __restrict__ dec,
            const float* __restrict__ th,
            float* __restrict__ out) {
    extern __shared__ float sth[];               // 32000 floats = 128 KB
    __shared__ float  redf[TPB / 32];
    __shared__ double redd[TPB / 32];
    __shared__ float  s_b[2];
    __shared__ int    s_last;

    const int tid = threadIdx.x;
    float4* sth4 = reinterpret_cast<float4*>(sth);
    const float4* th4 = reinterpret_cast<const float4*>(th);

    // prefetch this CTA's first row into L2 while prologue computes
    if (blockIdx.x < NROWS) {
        const float4* fp = row_ptr(p, blockIdx.x);
        #pragma unroll
        for (int q = 0; q < 8; q++) pf_l2(fp + tid + q * TPB);
    }

    for (int i = tid; i < V4; i += TPB) sth4[i] = th4[i];
    __syncthreads();

    // ---- prologue: usum ----
    {
        float s = 0.f;
        for (int i = tid; i < VOCAB; i += TPB) s += sth[i];
        s = warp_sum(s);
        if ((tid & 31) == 0) redf[tid >> 5] = s;
        __syncthreads();
        if (tid == 0) {
            float t = 0.f;
            #pragma unroll
            for (int w = 0; w < TPB / 32; w++) t += redf[w];
            s_b[0] = t;
        }
        __syncthreads();
    }
    const float usum  = s_b[0];
    const float inv01 = 0.1f / usum;

    // ---- prologue: C1 = sum f(eps*u_v) ----
    {
        float c = 0.f;
        for (int i = tid; i < VOCAB; i += TPB) {
            float x = sth[i] * inv01;
            c += x * lnfast(x);
        }
        c = warp_sum(c);
        if ((tid & 31) == 0) redf[tid >> 5] = c;
        __syncthreads();
        if (tid == 0) {
            float t = 0.f;
            #pragma unroll
            for (int w = 0; w < TPB / 32; w++) t += redf[w];
            s_b[1] = t;
        }
        __syncthreads();
    }
    const float C1 = s_b[1];

    double accD = 0.0;

    // ---- label-dependent O(1)-per-row terms ----
    {
        const int gid = blockIdx.x * TPB + tid;
        if (gid < NROWS) {
            const int b = gid / 1023;
            const int t = gid - b * 1023;
            const int l = __ldg(&dec[b * SEQ + t + 1]);
            if (l != 0) {
                float pl = __ldg(p + (size_t)(b * SEQ + t) * VOCAB + l);
                float x  = sth[l] * inv01;
                accD += (double)(C1
                                 - x * logf(x)
                                 + (x + 0.9f) * logf(x + 0.9f)
                                 - 0.9f * logf(pl));
            }
        }
    }

    // ---- bulk: cross-row pipelined MUFU loop, policy-hinted streaming loads ----
    const bool hasTail = (tid < TAILQ);
    const u64  pol     = mk_policy();
    float thrAcc = 0.f;

    int row = blockIdx.x;
    if (row < NROWS) {
        const float4* cp = row_ptr(p, row);
        // preload all 8 quads of the first row
        float4 q0 = ldstream(cp + tid,           pol);
        float4 q1 = ldstream(cp + tid + 1 * TPB, pol);
        float4 q2 = ldstream(cp + tid + 2 * TPB, pol);
        float4 q3 = ldstream(cp + tid + 3 * TPB, pol);
        float4 q4 = ldstream(cp + tid + 4 * TPB, pol);
        float4 q5 = ldstream(cp + tid + 5 * TPB, pol);
        float4 q6 = ldstream(cp + tid + 6 * TPB, pol);
        float4 q7;
        if (hasTail) q7 = ldstream(cp + tid + 7 * TPB, pol);

        while (true) {
            const int b   = row / 1023;
            const int lbl = __ldg(&dec[b * SEQ + (row - b * 1023) + 1]);

            float a0 = 0.f, a1 = 0.f;
            proc_quad(q0, sth4[tid          ], a0, a1);
            proc_quad(q1, sth4[tid + 1 * TPB], a0, a1);
            proc_quad(q2, sth4[tid + 2 * TPB], a0, a1);
            proc_quad(q3, sth4[tid + 3 * TPB], a0, a1);

            // refill head quads from the next row (re-read current on last iter)
            const int  nrow  = row + gridDim.x;
            const bool valid = (nrow < NROWS);
            const float4* np = valid ? row_ptr(p, nrow) : cp;
            q0 = ldstream(np + tid,           pol);
            q1 = ldstream(np + tid + 1 * TPB, pol);
            q2 = ldstream(np + tid + 2 * TPB, pol);
            q3 = ldstream(np + tid + 3 * TPB, pol);

            proc_quad(q4, sth4[tid + 4 * TPB], a0, a1);
            proc_quad(q5, sth4[tid + 5 * TPB], a0, a1);
            proc_quad(q6, sth4[tid + 6 * TPB], a0, a1);
            if (hasTail) proc_quad(q7, sth4[tid + 7 * TPB], a0, a1);

            // refill tail quads from the next row
            q4 = ldstream(np + tid + 4 * TPB, pol);
            q5 = ldstream(np + tid + 5 * TPB, pol);
            q6 = ldstream(np + tid + 6 * TPB, pol);
            if (hasTail) q7 = ldstream(np + tid + 7 * TPB, pol);

            if (lbl != 0) thrAcc += a0 + a1;

            if (!valid) break;
            row = nrow;
            cp  = np;
        }
    }

    // fold: accD += -eps/usum * ln2 * thrAcc
    accD += (double)thrAcc * (-0.1 * 0.6931471805599453 / (double)usum);

    // ---- per-CTA reduction ----
    accD = warp_sum_d(accD);
    if ((tid & 31) == 0) redd[tid >> 5] = accD;
    __syncthreads();
    if (tid == 0) {
        double t = 0.0;
        #pragma unroll
        for (int w = 0; w < TPB / 32; w++) t += redd[w];
        g_part[blockIdx.x] = t;
        __threadfence();
        unsigned old = atomicAdd(&g_cnt, 1u);
        s_last = (old == gridDim.x - 1) ? 1 : 0;
    }
    __syncthreads();

    // ---- last CTA finalizes ----
    if (s_last) {
        double v = (tid < (int)gridDim.x) ? g_part[tid] : 0.0;
        v = warp_sum_d(v);
        if ((tid & 31) == 0) redd[tid >> 5] = v;
        __syncthreads();
        if (tid == 0) {
            double t = 0.0;
            #pragma unroll
            for (int w = 0; w < TPB / 32; w++) t += redd[w];
            out[0] = (float)(t / (double)NROWS);
            g_cnt = 0;                 // reset for next graph replay
        }
    }
}

extern "C" void kernel_launch(void* const* d_in, const int* in_sizes, int n_in,
                              void* d_out, int out_size) {
    const int*   dec = nullptr;
    const float* p   = nullptr;
    const float* th  = nullptr;
    for (int i = 0; i < n_in; ++i) {
        if (in_sizes[i] == 4 * SEQ)    dec = (const int*)d_in[i];
        else if (in_sizes[i] == VOCAB) th  = (const float*)d_in[i];
        else                           p   = (const float*)d_in[i];
    }

    cudaFuncSetAttribute(main_kernel,
                         cudaFuncAttributeMaxDynamicSharedMemorySize,
                         VOCAB * (int)sizeof(float));

    int sms = 0;
    cudaDeviceGetAttribute(&sms, cudaDevAttrMultiProcessorCount, 0);
    if (sms <= 0) sms = 148;
    if (sms > MAXCTA) sms = MAXCTA;

    main_kernel<<<sms, TPB, VOCAB * sizeof(float)>>>(p, dec, th, (float*)d_out);
}

// round 15
// speedup vs baseline: 1.0050x; 1.0050x over previous
#include <cuda_runtime.h>
#include <math.h>

#define VOCAB   32000
#define V4      8000                 // float4 per row
#define NROWS   4092                 // 4 * 1023
#define SEQ     1024
#define TPB     1024
#define TAILQ   (V4 - 7 * TPB)       // 832 tail quads (= 26 full warps)
#define MAXCTA  256

__device__ double   g_part[MAXCTA];
__device__ unsigned g_cnt = 0;

// raw MUFU.LG2 (full-range log2 approx, single instruction)
__device__ __forceinline__ float lg2(float x) {
    float r; asm("lg2.approx.f32 %0, %1;" : "=f"(r) : "f"(x)); return r;
}

// streaming (evict-first) 128-bit load
__device__ __forceinline__ float4 ldcs4(const float4* a) {
    return __ldcs(a);
}

__device__ __forceinline__ void pf_l2(const void* ptr) {
    asm volatile("prefetch.global.L2 [%0];" :: "l"(ptr));
}

// scalar fast log (prologue only): degree-5, |abs err| <= 2e-4
__device__ __forceinline__ float lnfast(float x) {
    int i = __float_as_int(x);
    int k = (i - 0x3F2AAAAB) & 0xFF800000;
    float f = __int_as_float(i - k) - 1.0f;
    float P = 0.2f;
    P = fmaf(P, f, -0.25f);
    P = fmaf(P, f,  0.33333334f);
    P = fmaf(P, f, -0.5f);
    P = fmaf(P, f,  1.0f);
    return fmaf(f, P, (float)k * 8.2629582e-8f);
}

__device__ __forceinline__ float warp_sum(float v) {
    #pragma unroll
    for (int o = 16; o; o >>= 1) v += __shfl_xor_sync(0xFFFFFFFFu, v, o);
    return v;
}
__device__ __forceinline__ double warp_sum_d(double v) {
    #pragma unroll
    for (int o = 16; o; o >>= 1) v += __shfl_xor_sync(0xFFFFFFFFu, v, o);
    return v;
}

// one quad: 2-accumulator form
__device__ __forceinline__ void proc_quad(float4 v, float4 w, float& a0, float& a1) {
    a0 = fmaf(w.x, lg2(v.x), a0);
    a1 = fmaf(w.y, lg2(v.y), a1);
    a0 = fmaf(w.z, lg2(v.z), a0);
    a1 = fmaf(w.w, lg2(v.w), a1);
}

// row -> base quad pointer ( b*1024 + t = row + row/1023 )
__device__ __forceinline__ const float4* row_ptr(const float* p, int row) {
    int off = row + row / 1023;
    return reinterpret_cast<const float4*>(p + (size_t)off * VOCAB);
}

__global__ void __launch_bounds__(TPB, 1)
main_kernel(const float* __restrict__ p,
            const int*   __restrict__ dec,
            const float* __restrict__ th,
            float* __restrict__ out) {
    extern __shared__ float sth[];               // 32000 floats = 128 KB
    __shared__ float  redf[TPB / 32];
    __shared__ double redd[TPB / 32];
    __shared__ float  s_b[2];
    __shared__ int    s_last;

    const int tid = threadIdx.x;
    float4* sth4 = reinterpret_cast<float4*>(sth);
    const float4* th4 = reinterpret_cast<const float4*>(th);

    // prefetch this CTA's first row into L2 while the prologue computes
    if (blockIdx.x < NROWS) {
        const float4* fp = row_ptr(p, blockIdx.x);
        #pragma unroll
        for (int q = 0; q < 8; q++) pf_l2(fp + tid + q * TPB);
    }

    for (int i = tid; i < V4; i += TPB) sth4[i] = th4[i];
    __syncthreads();

    // ---- prologue: usum ----
    {
        float s = 0.f;
        for (int i = tid; i < VOCAB; i += TPB) s += sth[i];
        s = warp_sum(s);
        if ((tid & 31) == 0) redf[tid >> 5] = s;
        __syncthreads();
        if (tid == 0) {
            float t = 0.f;
            #pragma unroll
            for (int w = 0; w < TPB / 32; w++) t += redf[w];
            s_b[0] = t;
        }
        __syncthreads();
    }
    const float usum  = s_b[0];
    const float inv01 = 0.1f / usum;

    // ---- prologue: C1 = sum f(eps*u_v) ----
    {
        float c = 0.f;
        for (int i = tid; i < VOCAB; i += TPB) {
            float x = sth[i] * inv01;
            c += x * lnfast(x);
        }
        c = warp_sum(c);
        if ((tid & 31) == 0) redf[tid >> 5] = c;
        __syncthreads();
        if (tid == 0) {
            float t = 0.f;
            #pragma unroll
            for (int w = 0; w < TPB / 32; w++) t += redf[w];
            s_b[1] = t;
        }
        __syncthreads();
    }
    const float C1 = s_b[1];

    double accD = 0.0;

    // ---- label-dependent O(1)-per-row terms ----
    {
        const int gid = blockIdx.x * TPB + tid;
        if (gid < NROWS) {
            const int b = gid / 1023;
            const int t = gid - b * 1023;
            const int l = __ldg(&dec[b * SEQ + t + 1]);
            if (l != 0) {
                float pl = __ldg(p + (size_t)(b * SEQ + t) * VOCAB + l);
                float x  = sth[l] * inv01;
                accD += (double)(C1
                                 - x * logf(x)
                                 + (x + 0.9f) * logf(x + 0.9f)
                                 - 0.9f * logf(pl));
            }
        }
    }

    // ---- bulk: cross-row pipelined MUFU loop, streaming loads ----
    const bool hasTail = (tid < TAILQ);
    float thrAcc = 0.f;

    int row = blockIdx.x;
    if (row < NROWS) {
        const float4* cp = row_ptr(p, row);
        // preload all 8 quads of the first row
        float4 q0 = ldcs4(cp + tid);
        float4 q1 = ldcs4(cp + tid + 1 * TPB);
        float4 q2 = ldcs4(cp + tid + 2 * TPB);
        float4 q3 = ldcs4(cp + tid + 3 * TPB);
        float4 q4 = ldcs4(cp + tid + 4 * TPB);
        float4 q5 = ldcs4(cp + tid + 5 * TPB);
        float4 q6 = ldcs4(cp + tid + 6 * TPB);
        float4 q7;
        if (hasTail) q7 = ldcs4(cp + tid + 7 * TPB);

        while (true) {
            const int b   = row / 1023;
            const int lbl = __ldg(&dec[b * SEQ + (row - b * 1023) + 1]);

            const int  nrow  = row + gridDim.x;
            const bool valid = (nrow < NROWS);     // CTA-uniform
            const float4* np = row_ptr(p, nrow);   // only dereferenced if valid

            float a0 = 0.f, a1 = 0.f;
            proc_quad(q0, sth4[tid          ], a0, a1);
            proc_quad(q1, sth4[tid + 1 * TPB], a0, a1);
            proc_quad(q2, sth4[tid + 2 * TPB], a0, a1);
            proc_quad(q3, sth4[tid + 3 * TPB], a0, a1);

            // refill head quads from the next row (skipped on last iteration)
            if (valid) {
                q0 = ldcs4(np + tid);
                q1 = ldcs4(np + tid + 1 * TPB);
                q2 = ldcs4(np + tid + 2 * TPB);
                q3 = ldcs4(np + tid + 3 * TPB);
            }

            proc_quad(q4, sth4[tid + 4 * TPB], a0, a1);
            proc_quad(q5, sth4[tid + 5 * TPB], a0, a1);
            proc_quad(q6, sth4[tid + 6 * TPB], a0, a1);
            if (hasTail) proc_quad(q7, sth4[tid + 7 * TPB], a0, a1);

            // refill tail quads from the next row (skipped on last iteration)
            if (valid) {
                q4 = ldcs4(np + tid + 4 * TPB);
                q5 = ldcs4(np + tid + 5 * TPB);
                q6 = ldcs4(np + tid + 6 * TPB);
                if (hasTail) q7 = ldcs4(np + tid + 7 * TPB);
            }

            if (lbl != 0) thrAcc += a0 + a1;

            if (!valid) break;
            row = nrow;
            cp  = np;
        }
    }

    // fold: accD += -eps/usum * ln2 * thrAcc
    accD += (double)thrAcc * (-0.1 * 0.6931471805599453 / (double)usum);

    // ---- per-CTA reduction ----
    accD = warp_sum_d(accD);
    if ((tid & 31) == 0) redd[tid >> 5] = accD;
    __syncthreads();
    if (tid == 0) {
        double t = 0.0;
        #pragma unroll
        for (int w = 0; w < TPB / 32; w++) t += redd[w];
        g_part[blockIdx.x] = t;
        __threadfence();
        unsigned old = atomicAdd(&g_cnt, 1u);
        s_last = (old == gridDim.x - 1) ? 1 : 0;
    }
    __syncthreads();

    // ---- last CTA finalizes ----
    if (s_last) {
        double v = (tid < (int)gridDim.x) ? g_part[tid] : 0.0;
        v = warp_sum_d(v);
        if ((tid & 31) == 0) redd[tid >> 5] = v;
        __syncthreads();
        if (tid == 0) {
            double t = 0.0;
            #pragma unroll
            for (int w = 0; w < TPB / 32; w++) t += redd[w];
            out[0] = (float)(t / (double)NROWS);
            g_cnt = 0;                 // reset for next graph replay
        }
    }
}

extern "C" void kernel_launch(void* const* d_in, const int* in_sizes, int n_in,
                              void* d_out, int out_size) {
    const int*   dec = nullptr;
    const float* p   = nullptr;
    const float* th  = nullptr;
    for (int i = 0; i < n_in; ++i) {
        if (in_sizes[i] == 4 * SEQ)    dec = (const int*)d_in[i];
        else if (in_sizes[i] == VOCAB) th  = (const float*)d_in[i];
        else                           p   = (const float*)d_in[i];
    }

    cudaFuncSetAttribute(main_kernel,
                         cudaFuncAttributeMaxDynamicSharedMemorySize,
                         VOCAB * (int)sizeof(float));

    int sms = 0;
    cudaDeviceGetAttribute(&sms, cudaDevAttrMultiProcessorCount, 0);
    if (sms <= 0) sms = 148;
    if (sms > MAXCTA) sms = MAXCTA;

    main_kernel<<<sms, TPB, VOCAB * sizeof(float)>>>(p, dec, th, (float*)d_out);
}

// round 16
// speedup vs baseline: 1.0231x; 1.0181x over previous
#include <cuda_runtime.h>
#include <math.h>
#include <stdint.h>

#define VOCAB    32000
#define V4       8000                // float4 per row
#define NROWS    4092                // 4 * 1023
#define SEQ      1024
#define TPB      1024
#define TAILQ    (V4 - 7 * TPB)      // 832 tail quads (= 26 full warps)
#define MAXCTA   256
#define CLUSTER  2
#define TH_BYTES (VOCAB * 4)         // 128000

__device__ double   g_part[MAXCTA];
__device__ unsigned g_cnt = 0;

// ---------- mbarrier / bulk-async helpers ----------
__device__ __forceinline__ uint32_t smem_u32(const void* p) {
    uint32_t a;
    asm("{ .reg .u64 t; cvta.to.shared.u64 t, %1; cvt.u32.u64 %0, t; }" : "=r"(a) : "l"(p));
    return a;
}
__device__ __forceinline__ void mbar_init(uint32_t mbar, uint32_t cnt) {
    asm volatile("mbarrier.init.shared.b64 [%0], %1;" :: "r"(mbar), "r"(cnt) : "memory");
}
__device__ __forceinline__ void mbar_expect_tx(uint32_t mbar, uint32_t bytes) {
    asm volatile("mbarrier.arrive.expect_tx.shared.b64 _, [%0], %1;" :: "r"(mbar), "r"(bytes) : "memory");
}
__device__ __forceinline__ void mbar_wait(uint32_t mbar, uint32_t parity) {
    uint32_t done;
    asm volatile(
        "{\n\t.reg .pred p;\n\t"
        "mbarrier.try_wait.parity.acquire.cta.shared::cta.b64 p, [%1], %2;\n\t"
        "selp.b32 %0, 1, 0, p;\n\t}"
        : "=r"(done) : "r"(mbar), "r"(parity) : "memory");
    if (!done) {
        asm volatile(
            "{\n\t.reg .pred P1;\n\t"
            "WL_%=:\n\t"
            "mbarrier.try_wait.parity.acquire.cta.shared::cta.b64 P1, [%0], %1, 0x989680;\n\t"
            "@P1 bra.uni WD_%=;\n\t"
            "bra.uni WL_%=;\n\t"
            "WD_%=:\n\t}"
            :: "r"(mbar), "r"(parity) : "memory");
    }
}
// bulk copy global->shared, multicast to all cluster CTAs in mask
__device__ __forceinline__ void bulk_ld_mc(uint32_t dst, const void* src,
                                           uint32_t bytes, uint32_t mbar,
                                           uint16_t mask) {
    asm volatile(
        "cp.async.bulk.shared::cluster.global.mbarrier::complete_tx::bytes.multicast::cluster"
        " [%0], [%1], %2, [%3], %4;"
        :: "r"(dst), "l"(src), "r"(bytes), "r"(mbar), "h"(mask) : "memory");
}
__device__ __forceinline__ uint32_t cluster_rank() {
    uint32_t r; asm("mov.u32 %0, %%cluster_ctarank;" : "=r"(r)); return r;
}
#define CLUSTER_SYNC() do {                                           \
    asm volatile("barrier.cluster.arrive.aligned;" ::: "memory");     \
    asm volatile("barrier.cluster.wait.aligned;"   ::: "memory");     \
} while (0)

// raw MUFU.LG2 (full-range log2 approx, single instruction)
__device__ __forceinline__ float lg2(float x) {
    float r; asm("lg2.approx.f32 %0, %1;" : "=f"(r) : "f"(x)); return r;
}

// streaming (evict-first) 128-bit load
__device__ __forceinline__ float4 ldcs4(const float4* a) {
    return __ldcs(a);
}

__device__ __forceinline__ void pf_l2(const void* ptr) {
    asm volatile("prefetch.global.L2 [%0];" :: "l"(ptr));
}

// scalar fast log (prologue only): degree-5, |abs err| <= 2e-4
__device__ __forceinline__ float lnfast(float x) {
    int i = __float_as_int(x);
    int k = (i - 0x3F2AAAAB) & 0xFF800000;
    float f = __int_as_float(i - k) - 1.0f;
    float P = 0.2f;
    P = fmaf(P, f, -0.25f);
    P = fmaf(P, f,  0.33333334f);
    P = fmaf(P, f, -0.5f);
    P = fmaf(P, f,  1.0f);
    return fmaf(f, P, (float)k * 8.2629582e-8f);
}

__device__ __forceinline__ float warp_sum(float v) {
    #pragma unroll
    for (int o = 16; o; o >>= 1) v += __shfl_xor_sync(0xFFFFFFFFu, v, o);
    return v;
}
__device__ __forceinline__ double warp_sum_d(double v) {
    #pragma unroll
    for (int o = 16; o; o >>= 1) v += __shfl_xor_sync(0xFFFFFFFFu, v, o);
    return v;
}

// one quad: 2-accumulator form
__device__ __forceinline__ void proc_quad(float4 v, float4 w, float& a0, float& a1) {
    a0 = fmaf(w.x, lg2(v.x), a0);
    a1 = fmaf(w.y, lg2(v.y), a1);
    a0 = fmaf(w.z, lg2(v.z), a0);
    a1 = fmaf(w.w, lg2(v.w), a1);
}

// row -> base quad pointer ( b*1024 + t = row + row/1023 )
__device__ __forceinline__ const float4* row_ptr(const float* p, int row) {
    int off = row + row / 1023;
    return reinterpret_cast<const float4*>(p + (size_t)off * VOCAB);
}

__global__ void __launch_bounds__(TPB, 1) __cluster_dims__(CLUSTER, 1, 1)
main_kernel(const float* __restrict__ p,
            const int*   __restrict__ dec,
            const float* __restrict__ th,
            float* __restrict__ out) {
    extern __shared__ float sth[];               // 32000 floats = 128 KB
    __shared__ float  redf[TPB / 32];
    __shared__ double redd[TPB / 32];
    __shared__ float  s_b[2];
    __shared__ int    s_last;
    __shared__ alignas(8) unsigned long long mbar_store;

    const int tid = threadIdx.x;
    const uint32_t mb = smem_u32(&mbar_store);
    float4* sth4 = reinterpret_cast<float4*>(sth);

    // init mbarrier + set expected tx on this CTA's barrier
    if (tid == 0) {
        mbar_init(mb, 1);
        mbar_expect_tx(mb, TH_BYTES);
    }

    // prefetch this CTA's first row into L2 while th loads / prologue computes
    if (blockIdx.x < NROWS) {
        const float4* fp = row_ptr(p, blockIdx.x);
        #pragma unroll
        for (int q = 0; q < 8; q++) pf_l2(fp + tid + q * TPB);
    }
    __syncthreads();

    // both CTAs' barriers initialized before the multicast fires
    CLUSTER_SYNC();

    // cluster leader multicasts th into BOTH CTAs' smem (one LTS service)
    if (cluster_rank() == 0 && tid == 0) {
        bulk_ld_mc(smem_u32(sth), th, TH_BYTES, mb, (uint16_t)((1u << CLUSTER) - 1u));
    }
    mbar_wait(mb, 0);

    // ---- prologue: usum ----
    {
        float s = 0.f;
        for (int i = tid; i < VOCAB; i += TPB) s += sth[i];
        s = warp_sum(s);
        if ((tid & 31) == 0) redf[tid >> 5] = s;
        __syncthreads();
        if (tid == 0) {
            float t = 0.f;
            #pragma unroll
            for (int w = 0; w < TPB / 32; w++) t += redf[w];
            s_b[0] = t;
        }
        __syncthreads();
    }
    const float usum  = s_b[0];
    const float inv01 = 0.1f / usum;

    // ---- prologue: C1 = sum f(eps*u_v) ----
    {
        float c = 0.f;
        for (int i = tid; i < VOCAB; i += TPB) {
            float x = sth[i] * inv01;
            c += x * lnfast(x);
        }
        c = warp_sum(c);
        if ((tid & 31) == 0) redf[tid >> 5] = c;
        __syncthreads();
        if (tid == 0) {
            float t = 0.f;
            #pragma unroll
            for (int w = 0; w < TPB / 32; w++) t += redf[w];
            s_b[1] = t;
        }
        __syncthreads();
    }
    const float C1 = s_b[1];

    double accD = 0.0;

    // ---- label-dependent O(1)-per-row terms ----
    {
        const int gid = blockIdx.x * TPB + tid;
        if (gid < NROWS) {
            const int b = gid / 1023;
            const int t = gid - b * 1023;
            const int l = __ldg(&dec[b * SEQ + t + 1]);
            if (l != 0) {
                float pl = __ldg(p + (size_t)(b * SEQ + t) * VOCAB + l);
                float x  = sth[l] * inv01;
                accD += (double)(C1
                                 - x * logf(x)
                                 + (x + 0.9f) * logf(x + 0.9f)
                                 - 0.9f * logf(pl));
            }
        }
    }

    // ---- bulk: cross-row pipelined MUFU loop, streaming loads ----
    const bool hasTail = (tid < TAILQ);
    float thrAcc = 0.f;

    int row = blockIdx.x;
    if (row < NROWS) {
        const float4* cp = row_ptr(p, row);
        // preload all 8 quads of the first row
        float4 q0 = ldcs4(cp + tid);
        float4 q1 = ldcs4(cp + tid + 1 * TPB);
        float4 q2 = ldcs4(cp + tid + 2 * TPB);
        float4 q3 = ldcs4(cp + tid + 3 * TPB);
        float4 q4 = ldcs4(cp + tid + 4 * TPB);
        float4 q5 = ldcs4(cp + tid + 5 * TPB);
        float4 q6 = ldcs4(cp + tid + 6 * TPB);
        float4 q7;
        if (hasTail) q7 = ldcs4(cp + tid + 7 * TPB);

        while (true) {
            const int b   = row / 1023;
            const int lbl = __ldg(&dec[b * SEQ + (row - b * 1023) + 1]);

            const int  nrow  = row + gridDim.x;
            const bool valid = (nrow < NROWS);     // CTA-uniform
            const float4* np = row_ptr(p, nrow);   // only dereferenced if valid

            float a0 = 0.f, a1 = 0.f;
            proc_quad(q0, sth4[tid          ], a0, a1);
            proc_quad(q1, sth4[tid + 1 * TPB], a0, a1);
            proc_quad(q2, sth4[tid + 2 * TPB], a0, a1);
            proc_quad(q3, sth4[tid + 3 * TPB], a0, a1);

            if (valid) {
                q0 = ldcs4(np + tid);
                q1 = ldcs4(np + tid + 1 * TPB);
                q2 = ldcs4(np + tid + 2 * TPB);
                q3 = ldcs4(np + tid + 3 * TPB);
            }

            proc_quad(q4, sth4[tid + 4 * TPB], a0, a1);
            proc_quad(q5, sth4[tid + 5 * TPB], a0, a1);
            proc_quad(q6, sth4[tid + 6 * TPB], a0, a1);
            if (hasTail) proc_quad(q7, sth4[tid + 7 * TPB], a0, a1);

            if (valid) {
                q4 = ldcs4(np + tid + 4 * TPB);
                q5 = ldcs4(np + tid + 5 * TPB);
                q6 = ldcs4(np + tid + 6 * TPB);
                if (hasTail) q7 = ldcs4(np + tid + 7 * TPB);
            }

            if (lbl != 0) thrAcc += a0 + a1;

            if (!valid) break;
            row = nrow;
            cp  = np;
        }
    }

    // fold: accD += -eps/usum * ln2 * thrAcc
    accD += (double)thrAcc * (-0.1 * 0.6931471805599453 / (double)usum);

    // ---- per-CTA reduction ----
    accD = warp_sum_d(accD);
    if ((tid & 31) == 0) redd[tid >> 5] = accD;
    __syncthreads();
    if (tid == 0) {
        double t = 0.0;
        #pragma unroll
        for (int w = 0; w < TPB / 32; w++) t += redd[w];
        g_part[blockIdx.x] = t;
        __threadfence();
        unsigned old = atomicAdd(&g_cnt, 1u);
        s_last = (old == gridDim.x - 1) ? 1 : 0;
    }
    __syncthreads();

    // ---- last CTA finalizes ----
    if (s_last) {
        double v = (tid < (int)gridDim.x) ? g_part[tid] : 0.0;
        v = warp_sum_d(v);
        if ((tid & 31) == 0) redd[tid >> 5] = v;
        __syncthreads();
        if (tid == 0) {
            double t = 0.0;
            #pragma unroll
            for (int w = 0; w < TPB / 32; w++) t += redd[w];
            out[0] = (float)(t / (double)NROWS);
            g_cnt = 0;                 // reset for next graph replay
        }
    }

    // cluster lifetime safety: no CTA exits while a peer may still be served
    CLUSTER_SYNC();
}

extern "C" void kernel_launch(void* const* d_in, const int* in_sizes, int n_in,
                              void* d_out, int out_size) {
    const int*   dec = nullptr;
    const float* p   = nullptr;
    const float* th  = nullptr;
    for (int i = 0; i < n_in; ++i) {
        if (in_sizes[i] == 4 * SEQ)    dec = (const int*)d_in[i];
        else if (in_sizes[i] == VOCAB) th  = (const float*)d_in[i];
        else                           p   = (const float*)d_in[i];
    }

    cudaFuncSetAttribute(main_kernel,
                         cudaFuncAttributeMaxDynamicSharedMemorySize,
                         TH_BYTES);

    int sms = 0;
    cudaDeviceGetAttribute(&sms, cudaDevAttrMultiProcessorCount, 0);
    if (sms <= 0) sms = 148;
    if (sms > MAXCTA) sms = MAXCTA;
    sms -= sms % CLUSTER;            // grid must be divisible by cluster size

    main_kernel<<<sms, TPB, TH_BYTES>>>(p, dec, th, (float*)d_out);
}